// round 2
// baseline (speedup 1.0000x reference)
#include <cuda_runtime.h>
#include <math.h>
#include <stdint.h>

// ======================= problem dimensions =======================
constexpr int  NB    = 64;            // batch
constexpr int  S     = 196;           // patches (14x14)
constexpr int  D     = 256;           // hidden dim
constexpr long ROWS  = (long)NB * S;  // 12544

// ======================= scratch layout (floats) =======================
constexpr long SZ_COL = ROWS * 2304;          // im2col buffer (max K = 256*9)
constexpr long SZ_BSD = ROWS * 256;           // [B,S,256] tensors

constexpr long O_COL  = 0;
constexpr long O_Y    = O_COL  + SZ_COL;
constexpr long O_SC   = O_Y    + SZ_BSD;                  // scores [B,196,196]
constexpr long O_REA  = O_SC   + (long)NB * S * S;
constexpr long O_RE2  = O_REA  + SZ_BSD;
constexpr long O_PRE1 = O_RE2  + SZ_BSD;
constexpr long O_OUT  = O_PRE1 + SZ_BSD;
constexpr long O_R1   = O_OUT  + SZ_BSD;
constexpr long O_R2   = O_R1   + ROWS * 128;
constexpr long O_R3   = O_R2   + ROWS * 64;
constexpr long O_R3T  = O_R3   + ROWS * 32;
constexpr long O_PART = O_R3T  + ROWS * 32;               // split-K partials
constexpr long SZ_PART = 2097152;                          // >= 32*64*1024 and 8*64*3136
constexpr long O_RFC  = O_PART + SZ_PART;
constexpr long O_H1   = O_RFC  + 64L * 3136;
constexpr long O_REX  = O_H1   + SZ_BSD;
constexpr long O_OUT1 = O_REX  + SZ_BSD;
constexpr long O_OT   = O_OUT1 + SZ_BSD;                  // bn2 out, [b][c][s]
constexpr long O_OFC  = O_OT   + SZ_BSD;
constexpr long O_BS1  = O_OFC  + 64L * 1024;              // bn partial sums [64][256]
constexpr long O_BS2  = O_BS1  + 64L * 256;
constexpr long O_MEAN = O_BS2  + 64L * 256;
constexpr long O_ISTD = O_MEAN + 256;
constexpr long O_SCAL = O_ISTD + 256;                     // gate scale [64]
constexpr long O_RC1P = O_SCAL + 64;
constexpr long O_RC2P = O_RC1P + 128L * 2304;
constexpr long O_RC3P = O_RC2P + 64L * 1152;
constexpr long O_EW1P = O_RC3P + 32L * 576;
constexpr long O_EW2P = O_EW1P + 8L * 256 * 2304;
constexpr long O_END  = O_EW2P + 8L * 256 * 2304;

__device__ float g_scratch[O_END];
__device__ int   g_pos[64];

// ======================= device helpers =======================
__device__ __forceinline__ float geluf(float v) {
    return 0.5f * v * (1.0f + erff(v * 0.70710678118654752440f));
}
__device__ __forceinline__ unsigned long long pk2(float a, float b) {
    unsigned long long r;
    asm("mov.b64 %0, {%1, %2};" : "=l"(r) : "f"(a), "f"(b));
    return r;
}
__device__ __forceinline__ void fma2(unsigned long long& d,
                                     unsigned long long a, unsigned long long b) {
    asm("fma.rn.f32x2 %0, %1, %2, %0;" : "+l"(d) : "l"(a), "l"(b));
}
__device__ __forceinline__ float2 up2(unsigned long long v) {
    float a, b;
    asm("mov.b64 {%0, %1}, %2;" : "=f"(a), "=f"(b) : "l"(v));
    return make_float2(a, b);
}

// ======================= generic fp32 GEMM =======================
// C[M,N] = act(alpha * A[M,K] @ op(B) + bias) * zscale
//   B_NK=true : B is [N,K] row-major (weights / Y^T)
//   B_NK=false: B is [K,N] row-major
//   SPLIT=true: blockIdx.z = k-split, writes partials to C + z*M*N (no bias/act)
//   else      : blockIdx.z = batch; B (and bias) offset by bIdx[z] if given.
template<bool B_NK, bool SPLIT>
__global__ __launch_bounds__(256) void k_gemm(
    const float* __restrict__ A, const float* __restrict__ Bm, float* __restrict__ C,
    int M, int N, int K,
    long sA, long sB, long sC,
    const int* __restrict__ bIdx,
    const float* __restrict__ bias, long sBias,
    const float* __restrict__ zscale,
    float alpha, int act, int nsplit)
{
    __shared__ __align__(16) float As[16][68];
    __shared__ __align__(16) float Bs[16][68];

    const int z = blockIdx.z;
    int kBeg = 0, kEnd = K;
    float zs = 1.0f;
    const float* biasP = nullptr;
    if (SPLIT) {
        int kc = (K + nsplit - 1) / nsplit;
        kBeg = z * kc;
        kEnd = min(K, kBeg + kc);
        C += (long)z * M * N;
    } else {
        A += (long)z * sA;
        int bi = bIdx ? bIdx[z] : z;
        Bm += (long)bi * sB;
        C += (long)z * sC;
        if (bias) biasP = bias + (long)bi * sBias;
        if (zscale) zs = zscale[z];
    }

    const int tid = threadIdx.x;
    const int m0 = blockIdx.y * 64;
    const int n0 = blockIdx.x * 64;
    const int tr = tid >> 4;     // 0..15
    const int tc = tid & 15;     // 0..15

    unsigned long long acc[4][2];
#pragma unroll
    for (int i = 0; i < 4; i++) { acc[i][0] = 0ULL; acc[i][1] = 0ULL; }

    for (int k0 = kBeg; k0 < kEnd; k0 += 16) {
        // load A tile (64x16) -> As[k][m]
#pragma unroll
        for (int i = 0; i < 4; i++) {
            int f  = tid + i * 256;
            int m  = f >> 4;
            int kk = f & 15;
            int gm = m0 + m, gk = k0 + kk;
            As[kk][m] = (gm < M && gk < kEnd) ? A[(long)gm * K + gk] : 0.0f;
        }
        // load B tile (64x16) -> Bs[k][n]
#pragma unroll
        for (int i = 0; i < 4; i++) {
            int f = tid + i * 256;
            if (B_NK) {
                int n  = f >> 4;
                int kk = f & 15;
                int gn = n0 + n, gk = k0 + kk;
                Bs[kk][n] = (gn < N && gk < kEnd) ? Bm[(long)gn * K + gk] : 0.0f;
            } else {
                int n  = f & 63;
                int kk = f >> 6;
                int gn = n0 + n, gk = k0 + kk;
                Bs[kk][n] = (gn < N && gk < kEnd) ? Bm[(long)gk * N + gn] : 0.0f;
            }
        }
        __syncthreads();
#pragma unroll
        for (int kk = 0; kk < 16; kk++) {
            float4 av = *(const float4*)&As[kk][tr * 4];
            ulonglong2 bp = *(const ulonglong2*)&Bs[kk][tc * 4];
            unsigned long long a0 = pk2(av.x, av.x);
            unsigned long long a1 = pk2(av.y, av.y);
            unsigned long long a2 = pk2(av.z, av.z);
            unsigned long long a3 = pk2(av.w, av.w);
            fma2(acc[0][0], a0, bp.x); fma2(acc[0][1], a0, bp.y);
            fma2(acc[1][0], a1, bp.x); fma2(acc[1][1], a1, bp.y);
            fma2(acc[2][0], a2, bp.x); fma2(acc[2][1], a2, bp.y);
            fma2(acc[3][0], a3, bp.x); fma2(acc[3][1], a3, bp.y);
        }
        __syncthreads();
    }

    // epilogue
#pragma unroll
    for (int i = 0; i < 4; i++) {
        int gm = m0 + tr * 4 + i;
        if (gm >= M) continue;
#pragma unroll
        for (int jp = 0; jp < 2; jp++) {
            float2 v = up2(acc[i][jp]);
#pragma unroll
            for (int e = 0; e < 2; e++) {
                int gn = n0 + tc * 4 + jp * 2 + e;
                if (gn >= N) continue;
                float val = (e ? v.y : v.x) * alpha;
                if (biasP) val += biasP[gn];
                if (act == 1) val = geluf(val);
                val *= zs;
                C[(long)gm * N + gn] = val;
            }
        }
    }
}

// ======================= small kernels =======================
__global__ void k_permute3x3(const float* __restrict__ src, float* __restrict__ dst,
                             int Nout, int Cin) {
    long total = (long)Nout * Cin * 9;
    for (long i = blockIdx.x * (long)blockDim.x + threadIdx.x; i < total;
         i += (long)gridDim.x * blockDim.x) {
        int n = (int)(i / (Cin * 9));
        int r = (int)(i % (Cin * 9));
        int off = r / Cin, c = r % Cin;
        dst[i] = src[((long)n * Cin + c) * 9 + off];
    }
}

__global__ void k_im2col_patch(const float* __restrict__ x, float* __restrict__ dst) {
    long total = ROWS * 768;
    for (long i = blockIdx.x * (long)blockDim.x + threadIdx.x; i < total;
         i += (long)gridDim.x * blockDim.x) {
        int row = (int)(i / 768), k = (int)(i % 768);
        int b = row / 196, s = row % 196;
        int ph = s / 14, pw = s % 14;
        int c = k >> 8, r = k & 255, ii = r >> 4, jj = r & 15;
        dst[i] = x[(((long)(b * 3 + c) * 224) + ph * 16 + ii) * 224 + pw * 16 + jj];
    }
}

__global__ void k_im2col3(const float* __restrict__ src, float* __restrict__ dst, int Cin) {
    int K = 9 * Cin;
    long total = ROWS * K;
    for (long i = blockIdx.x * (long)blockDim.x + threadIdx.x; i < total;
         i += (long)gridDim.x * blockDim.x) {
        int row = (int)(i / K), k = (int)(i % K);
        int off = k / Cin, c = k % Cin;
        int b = row / 196, s = row % 196;
        int yy = s / 14, xx = s % 14;
        int sy = yy + off / 3 - 1, sx = xx + off % 3 - 1;
        float v = 0.0f;
        if ((unsigned)sy < 14u && (unsigned)sx < 14u)
            v = src[((long)(b * 196 + sy * 14 + sx)) * Cin + c];
        dst[i] = v;
    }
}

__global__ void k_addpos(float* __restrict__ y, const float* __restrict__ pos) {
    long total = ROWS * 256;
    for (long i = blockIdx.x * (long)blockDim.x + threadIdx.x; i < total;
         i += (long)gridDim.x * blockDim.x)
        y[i] += pos[i % (196 * 256)];
}

__global__ void k_add(float* __restrict__ dst, const float* __restrict__ a,
                      const float* __restrict__ b, long n) {
    for (long i = blockIdx.x * (long)blockDim.x + threadIdx.x; i < n;
         i += (long)gridDim.x * blockDim.x)
        dst[i] = a[i] + b[i];
}

__global__ void k_softmax(float* __restrict__ sc) {
    long row = blockIdx.x;                 // 12544 rows of 196
    float* p = sc + row * 196;
    int t = threadIdx.x;                   // 256 threads
    __shared__ float red[256];
    float v = (t < 196) ? p[t] : -3.4e38f;
    red[t] = v;
    __syncthreads();
    for (int s = 128; s > 0; s >>= 1) { if (t < s) red[t] = fmaxf(red[t], red[t + s]); __syncthreads(); }
    float mx = red[0];
    __syncthreads();
    float ex = (t < 196) ? expf(v - mx) : 0.0f;
    red[t] = ex;
    __syncthreads();
    for (int s = 128; s > 0; s >>= 1) { if (t < s) red[t] += red[t + s]; __syncthreads(); }
    float inv = 1.0f / red[0];
    if (t < 196) p[t] = ex * inv;
}

// deterministic BN stats: 64 chunks x 196 rows, thread = channel
__global__ void k_bnstat(const float* __restrict__ x, float* __restrict__ psum,
                         float* __restrict__ psq) {
    int c = threadIdx.x;       // 0..255
    int ch = blockIdx.x;       // 0..63
    float s = 0.0f, q = 0.0f;
    long r0 = (long)ch * 196;
    for (int r = 0; r < 196; r++) {
        float v = x[(r0 + r) * 256 + c];
        s += v;
        q += v * v;
    }
    psum[ch * 256 + c] = s;
    psq[ch * 256 + c]  = q;
}
__global__ void k_bnfin(const float* __restrict__ psum, const float* __restrict__ psq,
                        float* __restrict__ mean, float* __restrict__ istd) {
    int c = threadIdx.x;
    float s = 0.0f, q = 0.0f;
    for (int i = 0; i < 64; i++) { s += psum[i * 256 + c]; q += psq[i * 256 + c]; }
    float m = s / 12544.0f;
    float var = q / 12544.0f - m * m;
    mean[c] = m;
    istd[c] = rsqrtf(var + 1e-5f);
}
__global__ void k_bnnorm(const float* __restrict__ x, float* __restrict__ out,
                         const float* __restrict__ mean, const float* __restrict__ istd,
                         const float* __restrict__ g, const float* __restrict__ b,
                         int transposed) {
    long total = ROWS * 256;
    for (long i = blockIdx.x * (long)blockDim.x + threadIdx.x; i < total;
         i += (long)gridDim.x * blockDim.x) {
        int c = (int)(i & 255);
        long row = i >> 8;
        float v = (x[i] - mean[c]) * istd[c] * g[c] + b[c];
        if (!transposed) {
            out[i] = v;
        } else {
            int bb = (int)(row / 196), ss = (int)(row % 196);
            out[(long)bb * 50176 + c * 196 + ss] = v;
        }
    }
}

__global__ void k_tr32(const float* __restrict__ src, float* __restrict__ dst) {
    long total = ROWS * 32;
    for (long i = blockIdx.x * (long)blockDim.x + threadIdx.x; i < total;
         i += (long)gridDim.x * blockDim.x) {
        int b = (int)(i / 6272);
        int r = (int)(i % 6272);
        int c = r / 196, s = r % 196;
        dst[i] = src[((long)(b * 196 + s)) * 32 + c];
    }
}

__global__ void k_reduce(const float* __restrict__ part, float* __restrict__ out,
                         int M, int N, int nsplit, const float* __restrict__ bias, int act) {
    long total = (long)M * N;
    for (long i = blockIdx.x * (long)blockDim.x + threadIdx.x; i < total;
         i += (long)gridDim.x * blockDim.x) {
        int n = (int)(i % N);
        float s = 0.0f;
        for (int p = 0; p < nsplit; p++) s += part[(long)p * total + i];
        if (bias) s += bias[n];
        if (act) s = geluf(s);
        out[i] = s;
    }
}

// rd2 (8 experts) + argmax + gate, one block per sample
__global__ void k_rd2(const float* __restrict__ rfc, const float* __restrict__ w,
                      const float* __restrict__ b, int* __restrict__ pos,
                      float* __restrict__ scale) {
    int bb = blockIdx.x;
    int t = threadIdx.x;
    int e = t >> 5, lane = t & 31;
    const float* xr = rfc + (long)bb * 3136;
    const float* wr = w + (long)e * 3136;
    float s = 0.0f;
    for (int k = lane; k < 3136; k += 32) s += xr[k] * wr[k];
    for (int o = 16; o > 0; o >>= 1) s += __shfl_down_sync(0xffffffffu, s, o);
    __shared__ float lg[8];
    if (lane == 0) lg[e] = s + b[e];
    __syncthreads();
    if (t == 0) {
        int best = 0;
        float bv = lg[0];
        for (int e2 = 1; e2 < 8; e2++)
            if (lg[e2] > bv) { bv = lg[e2]; best = e2; }
        pos[bb] = best;
        scale[bb] = bv;
    }
}

// ======================= host-side launchers =======================
static inline int GS(long n) { return (int)((n + 255) / 256); }

static void gemm_nk(const float* A, const float* B, float* C, int M, int N, int K,
                    int Z, long sA, long sB, long sC,
                    const int* bIdx, const float* bias, long sBias,
                    const float* zscale, float alpha, int act) {
    dim3 g((N + 63) / 64, (M + 63) / 64, Z);
    k_gemm<true, false><<<g, 256>>>(A, B, C, M, N, K, sA, sB, sC,
                                    bIdx, bias, sBias, zscale, alpha, act, 1);
}
static void gemm_kn(const float* A, const float* B, float* C, int M, int N, int K,
                    int Z, long sA, long sB, long sC) {
    dim3 g((N + 63) / 64, (M + 63) / 64, Z);
    k_gemm<false, false><<<g, 256>>>(A, B, C, M, N, K, sA, sB, sC,
                                     nullptr, nullptr, 0, nullptr, 1.0f, 0, 1);
}
static void gemm_nk_split(const float* A, const float* B, float* part,
                          int M, int N, int K, int nsplit) {
    dim3 g((N + 63) / 64, (M + 63) / 64, nsplit);
    k_gemm<true, true><<<g, 256>>>(A, B, part, M, N, K, 0, 0, 0,
                                   nullptr, nullptr, 0, nullptr, 1.0f, 0, nsplit);
}

extern "C" void kernel_launch(void* const* d_in, const int* in_sizes, int n_in,
                              void* d_out, int out_size) {
    const float* x       = (const float*)d_in[0];
    const float* patch_w = (const float*)d_in[1];
    const float* patch_b = (const float*)d_in[2];
    const float* pos_emb = (const float*)d_in[3];
    const float* wo_w    = (const float*)d_in[4];
    const float* wo_b    = (const float*)d_in[5];
    const float* bn1_g   = (const float*)d_in[6];
    const float* bn1_b   = (const float*)d_in[7];
    const float* rc1_w   = (const float*)d_in[8];
    const float* rc1_b   = (const float*)d_in[9];
    const float* rc2_w   = (const float*)d_in[10];
    const float* rc2_b   = (const float*)d_in[11];
    const float* rc3_w   = (const float*)d_in[12];
    const float* rc3_b   = (const float*)d_in[13];
    const float* rd1_w   = (const float*)d_in[14];
    const float* rd1_b   = (const float*)d_in[15];
    const float* rd2_w   = (const float*)d_in[16];
    const float* rd2_b   = (const float*)d_in[17];
    const float* exp_w1  = (const float*)d_in[18];
    const float* exp_b1  = (const float*)d_in[19];
    const float* exp_w2  = (const float*)d_in[20];
    const float* exp_b2  = (const float*)d_in[21];
    const float* shard_w = (const float*)d_in[22];
    const float* shard_b = (const float*)d_in[23];
    const float* bn2_g   = (const float*)d_in[24];
    const float* bn2_b   = (const float*)d_in[25];
    const float* od1_w   = (const float*)d_in[26];
    const float* od1_b   = (const float*)d_in[27];
    const float* od2_w   = (const float*)d_in[28];
    const float* od2_b   = (const float*)d_in[29];

    float* Sb = nullptr;
    cudaGetSymbolAddress((void**)&Sb, g_scratch);
    int* posP = nullptr;
    cudaGetSymbolAddress((void**)&posP, g_pos);

    float* col   = Sb + O_COL;
    float* Y     = Sb + O_Y;
    float* sc    = Sb + O_SC;
    float* reA   = Sb + O_REA;
    float* re2   = Sb + O_RE2;
    float* pre1  = Sb + O_PRE1;
    float* outb  = Sb + O_OUT;
    float* r1    = Sb + O_R1;
    float* r2    = Sb + O_R2;
    float* r3    = Sb + O_R3;
    float* r3t   = Sb + O_R3T;
    float* part  = Sb + O_PART;
    float* rfc   = Sb + O_RFC;
    float* h1    = Sb + O_H1;
    float* rexp  = Sb + O_REX;
    float* out1  = Sb + O_OUT1;
    float* ot    = Sb + O_OT;
    float* ofc   = Sb + O_OFC;
    float* bs1   = Sb + O_BS1;
    float* bs2   = Sb + O_BS2;
    float* meanp = Sb + O_MEAN;
    float* istdp = Sb + O_ISTD;
    float* scalp = Sb + O_SCAL;
    float* rc1p  = Sb + O_RC1P;
    float* rc2p  = Sb + O_RC2P;
    float* rc3p  = Sb + O_RC3P;
    float* ew1p  = Sb + O_EW1P;
    float* ew2p  = Sb + O_EW2P;

    const float inv14 = 1.0f / sqrtf(14.0f);

    // ---- weight permutes: [Cout][Cin][3][3] -> [Cout][off*Cin + c] ----
    k_permute3x3<<<GS(128L * 2304), 256>>>(rc1_w, rc1p, 128, 256);
    k_permute3x3<<<GS(64L * 1152),  256>>>(rc2_w, rc2p, 64, 128);
    k_permute3x3<<<GS(32L * 576),   256>>>(rc3_w, rc3p, 32, 64);
    k_permute3x3<<<GS(2048L * 2304), 256>>>(exp_w1, ew1p, 2048, 256);
    k_permute3x3<<<GS(2048L * 2304), 256>>>(exp_w2, ew2p, 2048, 256);

    // ---- patch embedding -> Y [B,S,D], + pos_emb ----
    k_im2col_patch<<<GS(ROWS * 768), 256>>>(x, col);
    gemm_nk(col, patch_w, Y, 12544, 256, 768, 1, 0, 0, 0,
            nullptr, patch_b, 0, nullptr, 1.0f, 0);
    k_addpos<<<GS(ROWS * 256), 256>>>(Y, pos_emb);

    // ---- attention ----
    gemm_nk(Y, Y, sc, 196, 196, 256, NB, (long)S * D, (long)S * D, (long)S * S,
            nullptr, nullptr, 0, nullptr, inv14, 0);
    k_softmax<<<12544, 256>>>(sc);
    gemm_kn(sc, Y, reA, 196, 256, 196, NB, (long)S * S, (long)S * D, (long)S * D);
    gemm_nk(reA, wo_w, re2, 12544, 256, 256, 1, 0, 0, 0,
            nullptr, wo_b, 0, nullptr, 1.0f, 0);
    k_add<<<GS(ROWS * 256), 256>>>(pre1, Y, re2, ROWS * 256);

    // ---- bn1 -> out ----
    k_bnstat<<<64, 256>>>(pre1, bs1, bs2);
    k_bnfin<<<1, 256>>>(bs1, bs2, meanp, istdp);
    k_bnnorm<<<GS(ROWS * 256), 256>>>(pre1, outb, meanp, istdp, bn1_g, bn1_b, 0);

    // ---- router convs ----
    k_im2col3<<<GS(ROWS * 2304), 256>>>(outb, col, 256);
    gemm_nk(col, rc1p, r1, 12544, 128, 2304, 1, 0, 0, 0,
            nullptr, rc1_b, 0, nullptr, 1.0f, 1);
    k_im2col3<<<GS(ROWS * 1152), 256>>>(r1, col, 128);
    gemm_nk(col, rc2p, r2, 12544, 64, 1152, 1, 0, 0, 0,
            nullptr, rc2_b, 0, nullptr, 1.0f, 1);
    k_im2col3<<<GS(ROWS * 576), 256>>>(r2, col, 64);
    gemm_nk(col, rc3p, r3, 12544, 32, 576, 1, 0, 0, 0,
            nullptr, rc3_b, 0, nullptr, 1.0f, 1);
    k_tr32<<<GS(ROWS * 32), 256>>>(r3, r3t);

    // ---- router dense ----
    gemm_nk_split(r3t, rd1_w, part, 64, 3136, 6272, 8);
    k_reduce<<<GS(64L * 3136), 256>>>(part, rfc, 64, 3136, 8, rd1_b, 1);
    k_rd2<<<64, 256>>>(rfc, rd2_w, rd2_b, posP, scalp);

    // ---- experts (per-sample weight via posP) ----
    k_im2col3<<<GS(ROWS * 2304), 256>>>(re2, col, 256);
    gemm_nk(col, ew1p, h1, 196, 256, 2304, NB,
            (long)196 * 2304, (long)256 * 2304, (long)196 * 256,
            posP, exp_b1, 256, nullptr, 1.0f, 1);
    k_im2col3<<<GS(ROWS * 2304), 256>>>(h1, col, 256);
    gemm_nk(col, ew2p, rexp, 196, 256, 2304, NB,
            (long)196 * 2304, (long)256 * 2304, (long)196 * 256,
            posP, exp_b2, 256, scalp, 1.0f, 1);

    // ---- shard shortcut + sum + bn2 (transposed write [b][c][s]) ----
    gemm_nk(outb, shard_w, out1, 12544, 256, 256, 1, 0, 0, 0,
            nullptr, shard_b, 0, nullptr, 1.0f, 0);
    k_add<<<GS(ROWS * 256), 256>>>(rexp, rexp, out1, ROWS * 256);
    k_bnstat<<<64, 256>>>(rexp, bs1, bs2);
    k_bnfin<<<1, 256>>>(bs1, bs2, meanp, istdp);
    k_bnnorm<<<GS(ROWS * 256), 256>>>(rexp, ot, meanp, istdp, bn2_g, bn2_b, 1);

    // ---- output head ----
    gemm_nk_split(ot, od1_w, part, 64, 1024, 50176, 32);
    k_reduce<<<GS(64L * 1024), 256>>>(part, ofc, 64, 1024, 32, od1_b, 1);
    gemm_nk_split(ofc, od2_w, part, 64, 1000, 1024, 8);
    k_reduce<<<GS(64L * 1000), 256>>>(part, (float*)d_out, 64, 1000, 8, od2_b, 0);
}

// round 4
// speedup vs baseline: 1.9784x; 1.9784x over previous
#include <cuda_runtime.h>
#include <cuda_bf16.h>
#include <math.h>
#include <stdint.h>

constexpr int  NB   = 64;
constexpr long ROWS = 12544;

// ---------------- fp32 scratch ----------------
constexpr long O_Y=0, O_SC=O_Y+3211264, O_REA=O_SC+2458624, O_RE2=O_REA+3211264,
 O_PRE1=O_RE2+3211264, O_OUT=O_PRE1+3211264, O_R1=O_OUT+3211264, O_R2=O_R1+1605632,
 O_R3=O_R2+802816, O_R3T=O_R3+401408, O_PART=O_R3T+401408, O_RFC=O_PART+2097152,
 O_H1=O_RFC+200704, O_REX=O_H1+3211264, O_OUT1=O_REX+3211264, O_OT=O_OUT1+3211264,
 O_OFC=O_OT+3211264, O_BS1=O_OFC+65536, O_BS2=O_BS1+16384, O_MEAN=O_BS2+16384,
 O_ISTD=O_MEAN+256, O_SCAL=O_ISTD+256, O_FEND=O_SCAL+64;
__device__ float g_f[O_FEND];
__device__ int   g_pos[64];

// ---------------- bf16 scratch ----------------
constexpr long B_ABIG=0, B_YA=B_ABIG+113246208L, B_YB=B_YA+12582912L, B_YT=B_YB+12582912L,
 B_ATT=B_YT+10485760L, B_PW=B_ATT+10485760L, B_WO=B_PW+589824L, B_SH=B_WO+196608L,
 B_RC1=B_SH+196608L, B_RC2=B_RC1+884736L, B_RC3=B_RC2+442368L, B_EW1=B_RC3+221184L,
 B_EW2=B_EW1+14155776L, B_HEND=B_EW2+14155776L;
__device__ __align__(1024) __nv_bfloat16 g_h[B_HEND];

// ---------------- helpers ----------------
__device__ __forceinline__ uint32_t smem_u32(const void* p) {
    uint32_t a;
    asm("{ .reg .u64 t; cvta.to.shared.u64 t, %1; cvt.u32.u64 %0, t; }" : "=r"(a) : "l"(p));
    return a;
}
__device__ __forceinline__ float geluf(float v) {
    return 0.5f * v * (1.0f + erff(v * 0.70710678118654752440f));
}
#define CP_ASYNC16(dst, src) \
    asm volatile("cp.async.ca.shared.global [%0], [%1], 16;" :: "r"(dst), "l"(src))
#define CP_COMMIT() asm volatile("cp.async.commit_group;" ::: "memory")
#define CP_WAIT1()  asm volatile("cp.async.wait_group 1;" ::: "memory")
#define CP_WAIT0()  asm volatile("cp.async.wait_group 0;" ::: "memory")
#define LDSM_X4(r, addr) \
    asm volatile("ldmatrix.sync.aligned.m8n8.x4.shared.b16 {%0,%1,%2,%3}, [%4];" \
        : "=r"((r)[0]), "=r"((r)[1]), "=r"((r)[2]), "=r"((r)[3]) : "r"(addr))
__device__ __forceinline__ void mma16816(float* c, const uint32_t* a, uint32_t b0, uint32_t b1) {
    asm volatile("mma.sync.aligned.m16n8k16.row.col.f32.bf16.bf16.f32 "
        "{%0,%1,%2,%3}, {%4,%5,%6,%7}, {%8,%9}, {%0,%1,%2,%3};"
        : "+f"(c[0]), "+f"(c[1]), "+f"(c[2]), "+f"(c[3])
        : "r"(a[0]), "r"(a[1]), "r"(a[2]), "r"(a[3]), "r"(b0), "r"(b1));
}

// ---------------- tensor-core GEMM: C = act(alpha*A@B^T + bias)*zscale ----------------
// A [Mpad,Kp] bf16 K-major, B [Npad,Kp] bf16 K-major. CTA tile 128x128, K-chunk 32.
// 8 warps: warp tile 32(m) x 64(n). mma.sync m16n8k16 bf16, fp32 accum.
constexpr int SSTR = 40;   // padded smem row stride (bf16 elems) for conflict-free ldmatrix

__global__ __launch_bounds__(256) void k_tgemm(
    const __nv_bfloat16* __restrict__ A, const __nv_bfloat16* __restrict__ Bm,
    float* __restrict__ C, int M, int N, int Kp,
    long sA, long sB, long sC,
    const int* __restrict__ bIdx, const float* __restrict__ bias, long sBias,
    const float* __restrict__ zscale, float alpha, int act)
{
    __shared__ __align__(16) __nv_bfloat16 sA_[2][128][SSTR];
    __shared__ __align__(16) __nv_bfloat16 sB_[2][128][SSTR];

    const int tid = threadIdx.x, w = tid >> 5, lane = tid & 31;
    const int z = blockIdx.z, m0 = blockIdx.y * 128, n0 = blockIdx.x * 128;

    A += (long)z * sA;
    const int bi = bIdx ? bIdx[z] : z;
    Bm += (long)bi * sB;
    C += (long)z * sC;
    const float* biasP = bias ? bias + (long)bi * sBias : nullptr;
    const float zs = zscale ? zscale[z] : 1.0f;

    const uint32_t saB = smem_u32(&sA_[0][0][0]);
    const uint32_t sbB = smem_u32(&sB_[0][0][0]);

    const int wm = w & 3, wn = w >> 2;
    const int matId = lane >> 3;
    const int aRow = wm * 32 + (matId & 1) * 8 + (lane & 7);  // + mi*16
    const int aCol = (matId >> 1) * 8;                        // + k16*16
    const int bRow = wn * 64 + (matId >> 1) * 8 + (lane & 7); // + nj*16
    const int bCol = (matId & 1) * 8;                         // + k16*16

    float acc[2][8][4];
#pragma unroll
    for (int i = 0; i < 2; i++)
#pragma unroll
        for (int j = 0; j < 8; j++)
#pragma unroll
            for (int e = 0; e < 4; e++) acc[i][j][e] = 0.0f;

    const int nch = Kp >> 5;
    const int ldRow = tid >> 2, ldC8 = (tid & 3) << 3;        // seg it=0
    const int ldRow1 = (tid + 256) >> 2;                      // seg it=1 (same c8)

    // prefetch chunk 0
    {
        const __nv_bfloat16* Ab = A + (long)m0 * Kp;
        const __nv_bfloat16* Bb = Bm + (long)n0 * Kp;
        CP_ASYNC16(saB + (uint32_t)((ldRow * SSTR + ldC8) * 2),  Ab + (long)ldRow * Kp + ldC8);
        CP_ASYNC16(sbB + (uint32_t)((ldRow * SSTR + ldC8) * 2),  Bb + (long)ldRow * Kp + ldC8);
        CP_ASYNC16(saB + (uint32_t)((ldRow1 * SSTR + ldC8) * 2), Ab + (long)ldRow1 * Kp + ldC8);
        CP_ASYNC16(sbB + (uint32_t)((ldRow1 * SSTR + ldC8) * 2), Bb + (long)ldRow1 * Kp + ldC8);
        CP_COMMIT();
    }

    for (int ch = 0; ch < nch; ch++) {
        const int buf = ch & 1;
        if (ch + 1 < nch) {
            const int nb = buf ^ 1;
            const int k0 = (ch + 1) << 5;
            const __nv_bfloat16* Ab = A + (long)m0 * Kp + k0;
            const __nv_bfloat16* Bb = Bm + (long)n0 * Kp + k0;
            const uint32_t boff = (uint32_t)(nb * 128 * SSTR * 2);
            CP_ASYNC16(saB + boff + (uint32_t)((ldRow * SSTR + ldC8) * 2),  Ab + (long)ldRow * Kp + ldC8);
            CP_ASYNC16(sbB + boff + (uint32_t)((ldRow * SSTR + ldC8) * 2),  Bb + (long)ldRow * Kp + ldC8);
            CP_ASYNC16(saB + boff + (uint32_t)((ldRow1 * SSTR + ldC8) * 2), Ab + (long)ldRow1 * Kp + ldC8);
            CP_ASYNC16(sbB + boff + (uint32_t)((ldRow1 * SSTR + ldC8) * 2), Bb + (long)ldRow1 * Kp + ldC8);
            CP_COMMIT();
            CP_WAIT1();
        } else {
            CP_WAIT0();
        }
        __syncthreads();

        const uint32_t sa0 = saB + (uint32_t)(buf * 128 * SSTR * 2);
        const uint32_t sb0 = sbB + (uint32_t)(buf * 128 * SSTR * 2);
#pragma unroll
        for (int k16 = 0; k16 < 2; k16++) {
            uint32_t af[2][4];
#pragma unroll
            for (int mi = 0; mi < 2; mi++)
                LDSM_X4(af[mi], sa0 + (uint32_t)((((aRow + mi * 16) * SSTR) + aCol + k16 * 16) * 2));
            uint32_t bf[4][4];
#pragma unroll
            for (int nj = 0; nj < 4; nj++)
                LDSM_X4(bf[nj], sb0 + (uint32_t)((((bRow + nj * 16) * SSTR) + bCol + k16 * 16) * 2));
#pragma unroll
            for (int mi = 0; mi < 2; mi++)
#pragma unroll
                for (int nj = 0; nj < 4; nj++) {
                    mma16816(acc[mi][nj * 2],     af[mi], bf[nj][0], bf[nj][1]);
                    mma16816(acc[mi][nj * 2 + 1], af[mi], bf[nj][2], bf[nj][3]);
                }
        }
        __syncthreads();
    }

    // epilogue
#pragma unroll
    for (int mi = 0; mi < 2; mi++) {
#pragma unroll
        for (int nj2 = 0; nj2 < 8; nj2++) {
            int row0 = m0 + wm * 32 + mi * 16 + (lane >> 2);
            int col0 = n0 + wn * 64 + nj2 * 8 + (lane & 3) * 2;
#pragma unroll
            for (int half = 0; half < 2; half++) {
                int gm = row0 + half * 8;
                if (gm < M && col0 + 2 <= N) {
                    float2 o;
                    float v0 = acc[mi][nj2][half * 2]     * alpha;
                    float v1 = acc[mi][nj2][half * 2 + 1] * alpha;
                    if (biasP) { v0 += biasP[col0]; v1 += biasP[col0 + 1]; }
                    if (act) { v0 = geluf(v0); v1 = geluf(v1); }
                    o.x = v0 * zs; o.y = v1 * zs;
                    *(float2*)(C + (long)gm * N + col0) = o;
                }
            }
        }
    }
}

// ---------------- bf16x3 expansion kernels ----------------
__device__ __forceinline__ __nv_bfloat16 pick_hl(float x, bool lo) {
    __nv_bfloat16 hi = __float2bfloat16(x);
    return lo ? __float2bfloat16(x - __bfloat162float(hi)) : hi;
}

__global__ void k_expand8(const float* __restrict__ src, __nv_bfloat16* __restrict__ dst,
                          int Rvalid, int Rpad, int K, int Kp, long sSrc, int ld,
                          int trans, int orderB)
{
    long zr = blockIdx.y;
    int r = (int)(zr % Rpad), z = (int)(zr / Rpad);
    int kp0 = (blockIdx.x * blockDim.x + threadIdx.x) << 3;
    if (kp0 >= Kp) return;
    const float* sp = src + (long)z * sSrc;
    __nv_bfloat16 o[8];
#pragma unroll
    for (int j = 0; j < 8; j++) {
        int kp = kp0 + j;
        int seg = (kp >= K) + (kp >= 2 * K);
        int k = kp - seg * K;
        float x = 0.0f;
        if (r < Rvalid && kp < 3 * K)
            x = trans ? sp[(long)k * ld + r] : sp[(long)r * ld + k];
        o[j] = pick_hl(x, orderB ? (seg == 1) : (seg == 2));
    }
    *(uint4*)(dst + zr * Kp + kp0) = *(uint4*)o;
}

__global__ void k_exp_im2col3(const float* __restrict__ src, __nv_bfloat16* __restrict__ dst,
                              int Cin, int logC, int Kp, int perBatch)
{
    long row = blockIdx.y;
    int b, s; bool rv = true;
    if (perBatch) { b = (int)(row >> 8); int rp = (int)(row & 255); rv = rp < 196; s = rp; }
    else          { b = (int)(row / 196); s = (int)(row % 196); }
    const int K = 9 * Cin;
    int kp0 = (blockIdx.x * blockDim.x + threadIdx.x) << 3;
    if (kp0 >= Kp) return;
    __nv_bfloat16 o[8];
    float xv[8];
#pragma unroll
    for (int j = 0; j < 8; j++) xv[j] = 0.0f;
    int seg = (kp0 >= K) + (kp0 >= 2 * K);
    if (rv && kp0 < 3 * K) {
        int k = kp0 - seg * K;
        int off = k >> logC, c = k & (Cin - 1);
        int yy = s / 14, xx = s - yy * 14;
        int sy = yy + off / 3 - 1, sx = xx + off % 3 - 1;
        if ((unsigned)sy < 14u && (unsigned)sx < 14u) {
            const float* p = src + (((long)(b * 196 + sy * 14 + sx)) << logC) + c;
            float4 f0 = *(const float4*)p, f1 = *(const float4*)(p + 4);
            xv[0]=f0.x; xv[1]=f0.y; xv[2]=f0.z; xv[3]=f0.w;
            xv[4]=f1.x; xv[5]=f1.y; xv[6]=f1.z; xv[7]=f1.w;
        }
    }
    bool lo = (seg == 2);
#pragma unroll
    for (int j = 0; j < 8; j++) o[j] = pick_hl(xv[j], lo);
    *(uint4*)(dst + row * Kp + kp0) = *(uint4*)o;
}

__global__ void k_exp_patch(const float* __restrict__ x, __nv_bfloat16* __restrict__ dst)
{
    int row = blockIdx.y;
    int b = row / 196, s = row % 196;
    int ph = s / 14, pw = s - ph * 14;
    int kp0 = (blockIdx.x * blockDim.x + threadIdx.x) << 3;
    if (kp0 >= 2304) return;
    int seg = (kp0 >= 768) + (kp0 >= 1536);
    int k = kp0 - seg * 768;
    int c = k >> 8, ii = (k >> 4) & 15, jj = k & 15;
    const float* p = x + (((long)(b * 3 + c) * 224) + ph * 16 + ii) * 224 + pw * 16 + jj;
    float4 f0 = *(const float4*)p, f1 = *(const float4*)(p + 4);
    float xv[8] = {f0.x, f0.y, f0.z, f0.w, f1.x, f1.y, f1.z, f1.w};
    bool lo = (seg == 2);
    __nv_bfloat16 o[8];
#pragma unroll
    for (int j = 0; j < 8; j++) o[j] = pick_hl(xv[j], lo);
    *(uint4*)(dst + (long)row * 2304 + kp0) = *(uint4*)o;
}

__global__ void k_exp_w3x3(const float* __restrict__ src, __nv_bfloat16* __restrict__ dst,
                           int Nout, int Cin, int logC, int Kp)
{
    int n = blockIdx.y;
    const int K = 9 * Cin;
    int kp0 = (blockIdx.x * blockDim.x + threadIdx.x) << 3;
    if (kp0 >= Kp) return;
    __nv_bfloat16 o[8];
    int seg = (kp0 >= K) + (kp0 >= 2 * K);
    int k = kp0 - seg * K;
    int off = k >> logC, c = k & (Cin - 1);
    bool inb = (n < Nout) && (kp0 < 3 * K);
    bool lo = (seg == 1);
#pragma unroll
    for (int j = 0; j < 8; j++) {
        float xx = inb ? src[((long)n * Cin + c + j) * 9 + off] : 0.0f;
        o[j] = pick_hl(xx, lo);
    }
    *(uint4*)(dst + (long)n * Kp + kp0) = *(uint4*)o;
}

// ---------------- FFMA split-K (skinny M=64) ----------------
__device__ __forceinline__ unsigned long long pk2(float a, float b) {
    unsigned long long r;
    asm("mov.b64 %0, {%1, %2};" : "=l"(r) : "f"(a), "f"(b));
    return r;
}
__device__ __forceinline__ void fma2(unsigned long long& d,
                                     unsigned long long a, unsigned long long b) {
    asm("fma.rn.f32x2 %0, %1, %2, %0;" : "+l"(d) : "l"(a), "l"(b));
}
__device__ __forceinline__ float2 up2(unsigned long long v) {
    float a, b;
    asm("mov.b64 {%0, %1}, %2;" : "=f"(a), "=f"(b) : "l"(v));
    return make_float2(a, b);
}

__global__ __launch_bounds__(256) void k_gemm_split(
    const float* __restrict__ A, const float* __restrict__ Bm, float* __restrict__ C,
    int M, int N, int K, int nsplit)
{
    __shared__ __align__(16) float As[16][68];
    __shared__ __align__(16) float Bs[16][68];
    const int z = blockIdx.z;
    int kc = (K + nsplit - 1) / nsplit;
    int kBeg = z * kc, kEnd = min(K, kBeg + kc);
    C += (long)z * M * N;
    const int tid = threadIdx.x;
    const int m0 = blockIdx.y * 64, n0 = blockIdx.x * 64;
    const int tr = tid >> 4, tc = tid & 15;
    unsigned long long acc[4][2];
#pragma unroll
    for (int i = 0; i < 4; i++) { acc[i][0] = 0ULL; acc[i][1] = 0ULL; }
    for (int k0 = kBeg; k0 < kEnd; k0 += 16) {
#pragma unroll
        for (int i = 0; i < 4; i++) {
            int f = tid + i * 256;
            int m = f >> 4, kk = f & 15;
            int gm = m0 + m, gk = k0 + kk;
            As[kk][m] = (gm < M && gk < kEnd) ? A[(long)gm * K + gk] : 0.0f;
            int gn = n0 + m;
            Bs[kk][m] = (gn < N && gk < kEnd) ? Bm[(long)gn * K + gk] : 0.0f;
        }
        __syncthreads();
#pragma unroll
        for (int kk = 0; kk < 16; kk++) {
            float4 av = *(const float4*)&As[kk][tr * 4];
            ulonglong2 bp = *(const ulonglong2*)&Bs[kk][tc * 4];
            unsigned long long a0 = pk2(av.x, av.x), a1 = pk2(av.y, av.y);
            unsigned long long a2 = pk2(av.z, av.z), a3 = pk2(av.w, av.w);
            fma2(acc[0][0], a0, bp.x); fma2(acc[0][1], a0, bp.y);
            fma2(acc[1][0], a1, bp.x); fma2(acc[1][1], a1, bp.y);
            fma2(acc[2][0], a2, bp.x); fma2(acc[2][1], a2, bp.y);
            fma2(acc[3][0], a3, bp.x); fma2(acc[3][1], a3, bp.y);
        }
        __syncthreads();
    }
#pragma unroll
    for (int i = 0; i < 4; i++) {
        int gm = m0 + tr * 4 + i;
        if (gm >= M) continue;
#pragma unroll
        for (int jp = 0; jp < 2; jp++) {
            float2 v = up2(acc[i][jp]);
            int gn = n0 + tc * 4 + jp * 2;
            if (gn < N)     C[(long)gm * N + gn] = v.x;
            if (gn + 1 < N) C[(long)gm * N + gn + 1] = v.y;
        }
    }
}

// ---------------- small kernels ----------------
__global__ void k_addpos(float* __restrict__ y, const float* __restrict__ pos) {
    long total = ROWS * 256;
    for (long i = blockIdx.x * (long)blockDim.x + threadIdx.x; i < total;
         i += (long)gridDim.x * blockDim.x)
        y[i] += pos[i % (196 * 256)];
}
__global__ void k_add(float* __restrict__ dst, const float* __restrict__ a,
                      const float* __restrict__ b, long n) {
    for (long i = blockIdx.x * (long)blockDim.x + threadIdx.x; i < n;
         i += (long)gridDim.x * blockDim.x)
        dst[i] = a[i] + b[i];
}
__global__ void k_softmax(float* __restrict__ sc) {
    long row = blockIdx.x;
    float* p = sc + row * 196;
    int t = threadIdx.x;
    __shared__ float red[256];
    float v = (t < 196) ? p[t] : -3.4e38f;
    red[t] = v; __syncthreads();
    for (int s = 128; s > 0; s >>= 1) { if (t < s) red[t] = fmaxf(red[t], red[t + s]); __syncthreads(); }
    float mx = red[0]; __syncthreads();
    float ex = (t < 196) ? expf(v - mx) : 0.0f;
    red[t] = ex; __syncthreads();
    for (int s = 128; s > 0; s >>= 1) { if (t < s) red[t] += red[t + s]; __syncthreads(); }
    float inv = 1.0f / red[0];
    if (t < 196) p[t] = ex * inv;
}
__global__ void k_bnstat(const float* __restrict__ x, float* __restrict__ psum,
                         float* __restrict__ psq) {
    int c = threadIdx.x, ch = blockIdx.x;
    float s = 0.0f, q = 0.0f;
    long r0 = (long)ch * 196;
    for (int r = 0; r < 196; r++) {
        float v = x[(r0 + r) * 256 + c];
        s += v; q += v * v;
    }
    psum[ch * 256 + c] = s; psq[ch * 256 + c] = q;
}
__global__ void k_bnfin(const float* __restrict__ psum, const float* __restrict__ psq,
                        float* __restrict__ mean, float* __restrict__ istd) {
    int c = threadIdx.x;
    float s = 0.0f, q = 0.0f;
    for (int i = 0; i < 64; i++) { s += psum[i * 256 + c]; q += psq[i * 256 + c]; }
    float m = s / 12544.0f;
    float var = q / 12544.0f - m * m;
    mean[c] = m; istd[c] = rsqrtf(var + 1e-5f);
}
__global__ void k_bnnorm(const float* __restrict__ x, float* __restrict__ out,
                         const float* __restrict__ mean, const float* __restrict__ istd,
                         const float* __restrict__ g, const float* __restrict__ b,
                         int transposed) {
    long total = ROWS * 256;
    for (long i = blockIdx.x * (long)blockDim.x + threadIdx.x; i < total;
         i += (long)gridDim.x * blockDim.x) {
        int c = (int)(i & 255);
        long row = i >> 8;
        float v = (x[i] - mean[c]) * istd[c] * g[c] + b[c];
        if (!transposed) out[i] = v;
        else {
            int bb = (int)(row / 196), ss = (int)(row % 196);
            out[(long)bb * 50176 + c * 196 + ss] = v;
        }
    }
}
__global__ void k_tr32(const float* __restrict__ src, float* __restrict__ dst) {
    long total = ROWS * 32;
    for (long i = blockIdx.x * (long)blockDim.x + threadIdx.x; i < total;
         i += (long)gridDim.x * blockDim.x) {
        int b = (int)(i / 6272), r = (int)(i % 6272);
        int c = r / 196, s = r % 196;
        dst[i] = src[((long)(b * 196 + s)) * 32 + c];
    }
}
__global__ void k_reduce(const float* __restrict__ part, float* __restrict__ out,
                         int M, int N, int nsplit, const float* __restrict__ bias, int act) {
    long total = (long)M * N;
    for (long i = blockIdx.x * (long)blockDim.x + threadIdx.x; i < total;
         i += (long)gridDim.x * blockDim.x) {
        int n = (int)(i % N);
        float s = 0.0f;
        for (int p = 0; p < nsplit; p++) s += part[(long)p * total + i];
        if (bias) s += bias[n];
        if (act) s = geluf(s);
        out[i] = s;
    }
}
__global__ void k_rd2(const float* __restrict__ rfc, const float* __restrict__ w,
                      const float* __restrict__ b, int* __restrict__ pos,
                      float* __restrict__ scale) {
    int bb = blockIdx.x, t = threadIdx.x;
    int e = t >> 5, lane = t & 31;
    const float* xr = rfc + (long)bb * 3136;
    const float* wr = w + (long)e * 3136;
    float s = 0.0f;
    for (int k = lane; k < 3136; k += 32) s += xr[k] * wr[k];
    for (int o = 16; o > 0; o >>= 1) s += __shfl_down_sync(0xffffffffu, s, o);
    __shared__ float lg[8];
    if (lane == 0) lg[e] = s + b[e];
    __syncthreads();
    if (t == 0) {
        int best = 0; float bv = lg[0];
        for (int e2 = 1; e2 < 8; e2++) if (lg[e2] > bv) { bv = lg[e2]; best = e2; }
        pos[bb] = best; scale[bb] = bv;
    }
}

// ---------------- host ----------------
static inline int GS(long n) { return (int)((n + 255) / 256); }

static void tgemm(const __nv_bfloat16* A, const __nv_bfloat16* B, float* C,
                  int M, int Mpad, int N, int Npad, int Kp, int Z,
                  long sA, long sB, long sC,
                  const int* bIdx, const float* bias, long sBias,
                  const float* zscale, float alpha, int act) {
    dim3 g(Npad / 128, Mpad / 128, Z);
    k_tgemm<<<g, 256>>>(A, B, C, M, N, Kp, sA, sB, sC,
                        bIdx, bias, sBias, zscale, alpha, act);
}
static void expand8(const float* src, __nv_bfloat16* dst, int Rvalid, int Rpad,
                    int K, int Kp, long sSrc, int ld, int trans, int orderB, int Z) {
    dim3 g((Kp / 8 + 127) / 128, Z * Rpad);
    k_expand8<<<g, 128>>>(src, dst, Rvalid, Rpad, K, Kp, sSrc, ld, trans, orderB);
}
static void exp_im2col3(const float* src, __nv_bfloat16* dst, int Cin, int logC,
                        int Kp, int perBatch) {
    dim3 g((Kp / 8 + 127) / 128, perBatch ? 16384 : 12544);
    k_exp_im2col3<<<g, 128>>>(src, dst, Cin, logC, Kp, perBatch);
}

extern "C" void kernel_launch(void* const* d_in, const int* in_sizes, int n_in,
                              void* d_out, int out_size) {
    const float* x       = (const float*)d_in[0];
    const float* patch_w = (const float*)d_in[1];
    const float* patch_b = (const float*)d_in[2];
    const float* pos_emb = (const float*)d_in[3];
    const float* wo_w    = (const float*)d_in[4];
    const float* wo_b    = (const float*)d_in[5];
    const float* bn1_g   = (const float*)d_in[6];
    const float* bn1_b   = (const float*)d_in[7];
    const float* rc1_w   = (const float*)d_in[8];
    const float* rc1_b   = (const float*)d_in[9];
    const float* rc2_w   = (const float*)d_in[10];
    const float* rc2_b   = (const float*)d_in[11];
    const float* rc3_w   = (const float*)d_in[12];
    const float* rc3_b   = (const float*)d_in[13];
    const float* rd1_w   = (const float*)d_in[14];
    const float* rd1_b   = (const float*)d_in[15];
    const float* rd2_w   = (const float*)d_in[16];
    const float* rd2_b   = (const float*)d_in[17];
    const float* exp_w1  = (const float*)d_in[18];
    const float* exp_b1  = (const float*)d_in[19];
    const float* exp_w2  = (const float*)d_in[20];
    const float* exp_b2  = (const float*)d_in[21];
    const float* shard_w = (const float*)d_in[22];
    const float* shard_b = (const float*)d_in[23];
    const float* bn2_g   = (const float*)d_in[24];
    const float* bn2_b   = (const float*)d_in[25];
    const float* od1_w   = (const float*)d_in[26];
    const float* od1_b   = (const float*)d_in[27];
    const float* od2_w   = (const float*)d_in[28];
    const float* od2_b   = (const float*)d_in[29];

    float* F = nullptr;            cudaGetSymbolAddress((void**)&F, g_f);
    __nv_bfloat16* Hh = nullptr;   cudaGetSymbolAddress((void**)&Hh, g_h);
    int* posP = nullptr;           cudaGetSymbolAddress((void**)&posP, g_pos);

    float *Y = F + O_Y, *sc = F + O_SC, *reA = F + O_REA, *re2 = F + O_RE2;
    float *pre1 = F + O_PRE1, *outb = F + O_OUT, *r1 = F + O_R1, *r2 = F + O_R2;
    float *r3 = F + O_R3, *r3t = F + O_R3T, *part = F + O_PART, *rfc = F + O_RFC;
    float *h1 = F + O_H1, *rexp = F + O_REX, *out1 = F + O_OUT1, *ot = F + O_OT;
    float *ofc = F + O_OFC, *bs1 = F + O_BS1, *bs2 = F + O_BS2;
    float *meanp = F + O_MEAN, *istdp = F + O_ISTD, *scalp = F + O_SCAL;

    __nv_bfloat16 *ABig = Hh + B_ABIG, *YA = Hh + B_YA, *YB = Hh + B_YB, *YT = Hh + B_YT;
    __nv_bfloat16 *ATT = Hh + B_ATT, *PW = Hh + B_PW, *WO = Hh + B_WO, *SH = Hh + B_SH;
    __nv_bfloat16 *RC1 = Hh + B_RC1, *RC2 = Hh + B_RC2, *RC3 = Hh + B_RC3;
    __nv_bfloat16 *EW1 = Hh + B_EW1, *EW2 = Hh + B_EW2;

    const float inv14 = 1.0f / sqrtf(14.0f);

    // weight expansions (B-order)
    expand8(patch_w, PW, 256, 256, 768, 2304, 0, 768, 0, 1, 1);
    expand8(wo_w,    WO, 256, 256, 256, 768,  0, 256, 0, 1, 1);
    expand8(shard_w, SH, 256, 256, 256, 768,  0, 256, 0, 1, 1);
    { dim3 g(7, 128);  k_exp_w3x3<<<g, 128>>>(rc1_w, RC1, 128, 256, 8, 6912); }
    { dim3 g(4, 128);  k_exp_w3x3<<<g, 128>>>(rc2_w, RC2, 64, 128, 7, 3456); }
    { dim3 g(2, 128);  k_exp_w3x3<<<g, 128>>>(rc3_w, RC3, 32, 64, 6, 1728); }
    { dim3 g(7, 2048); k_exp_w3x3<<<g, 128>>>(exp_w1, EW1, 2048, 256, 8, 6912); }
    { dim3 g(7, 2048); k_exp_w3x3<<<g, 128>>>(exp_w2, EW2, 2048, 256, 8, 6912); }

    // patch embed -> Y
    { dim3 g(3, 12544); k_exp_patch<<<g, 128>>>(x, ABig); }
    tgemm(ABig, PW, Y, 12544, 12544, 256, 256, 2304, 1, 0, 0, 0,
          nullptr, patch_b, 0, nullptr, 1.0f, 0);
    k_addpos<<<GS(ROWS * 256), 256>>>(Y, pos_emb);

    // attention
    expand8(Y, YA, 196, 256, 256, 768, 196 * 256, 256, 0, 0, 64);
    expand8(Y, YB, 196, 256, 256, 768, 196 * 256, 256, 0, 1, 64);
    tgemm(YA, YB, sc, 196, 256, 196, 256, 768, 64, 256L * 768, 256L * 768, 196L * 196,
          nullptr, nullptr, 0, nullptr, inv14, 0);
    k_softmax<<<12544, 256>>>(sc);
    expand8(sc, ATT, 196, 256, 196, 640, 196 * 196, 196, 0, 0, 64);
    expand8(Y, YT, 256, 256, 196, 640, 196 * 256, 256, 1, 1, 64);
    tgemm(ATT, YT, reA, 196, 256, 256, 256, 640, 64, 256L * 640, 256L * 640, 196L * 256,
          nullptr, nullptr, 0, nullptr, 1.0f, 0);
    expand8(reA, ABig, 12544, 12544, 256, 768, 0, 256, 0, 0, 1);
    tgemm(ABig, WO, re2, 12544, 12544, 256, 256, 768, 1, 0, 0, 0,
          nullptr, wo_b, 0, nullptr, 1.0f, 0);
    k_add<<<GS(ROWS * 256), 256>>>(pre1, Y, re2, ROWS * 256);

    // bn1
    k_bnstat<<<64, 256>>>(pre1, bs1, bs2);
    k_bnfin<<<1, 256>>>(bs1, bs2, meanp, istdp);
    k_bnnorm<<<GS(ROWS * 256), 256>>>(pre1, outb, meanp, istdp, bn1_g, bn1_b, 0);

    // router convs
    exp_im2col3(outb, ABig, 256, 8, 6912, 0);
    tgemm(ABig, RC1, r1, 12544, 12544, 128, 128, 6912, 1, 0, 0, 0,
          nullptr, rc1_b, 0, nullptr, 1.0f, 1);
    exp_im2col3(r1, ABig, 128, 7, 3456, 0);
    tgemm(ABig, RC2, r2, 12544, 12544, 64, 128, 3456, 1, 0, 0, 0,
          nullptr, rc2_b, 0, nullptr, 1.0f, 1);
    exp_im2col3(r2, ABig, 64, 6, 1728, 0);
    tgemm(ABig, RC3, r3, 12544, 12544, 32, 128, 1728, 1, 0, 0, 0,
          nullptr, rc3_b, 0, nullptr, 1.0f, 1);
    k_tr32<<<GS(ROWS * 32), 256>>>(r3, r3t);

    // router dense (FFMA split-K) + argmax gate
    { dim3 g(49, 1, 8); k_gemm_split<<<g, 256>>>(r3t, rd1_w, part, 64, 3136, 6272, 8); }
    k_reduce<<<GS(64L * 3136), 256>>>(part, rfc, 64, 3136, 8, rd1_b, 1);
    k_rd2<<<64, 256>>>(rfc, rd2_w, rd2_b, posP, scalp);

    // shard shortcut (uses ABig before experts overwrite it)
    expand8(outb, ABig, 12544, 12544, 256, 768, 0, 256, 0, 0, 1);
    tgemm(ABig, SH, out1, 12544, 12544, 256, 256, 768, 1, 0, 0, 0,
          nullptr, shard_b, 0, nullptr, 1.0f, 0);

    // experts
    exp_im2col3(re2, ABig, 256, 8, 6912, 1);
    tgemm(ABig, EW1, h1, 196, 256, 256, 256, 6912, 64,
          256L * 6912, 256L * 6912, 196L * 256, posP, exp_b1, 256, nullptr, 1.0f, 1);
    exp_im2col3(h1, ABig, 256, 8, 6912, 1);
    tgemm(ABig, EW2, rexp, 196, 256, 256, 256, 6912, 64,
          256L * 6912, 256L * 6912, 196L * 256, posP, exp_b2, 256, scalp, 1.0f, 1);

    // sum + bn2 (transposed write [b][c][s])
    k_add<<<GS(ROWS * 256), 256>>>(rexp, rexp, out1, ROWS * 256);
    k_bnstat<<<64, 256>>>(rexp, bs1, bs2);
    k_bnfin<<<1, 256>>>(bs1, bs2, meanp, istdp);
    k_bnnorm<<<GS(ROWS * 256), 256>>>(rexp, ot, meanp, istdp, bn2_g, bn2_b, 1);

    // output head (FFMA split-K)
    { dim3 g(16, 1, 32); k_gemm_split<<<g, 256>>>(ot, od1_w, part, 64, 1024, 50176, 32); }
    k_reduce<<<GS(64L * 1024), 256>>>(part, ofc, 64, 1024, 32, od1_b, 1);
    { dim3 g(16, 1, 8); k_gemm_split<<<g, 256>>>(ofc, od2_w, part, 64, 1000, 1024, 8); }
    k_reduce<<<GS(64L * 1000), 256>>>(part, (float*)d_out, 64, 1000, 8, od2_b, 0);
}

// round 5
// speedup vs baseline: 2.1456x; 1.0845x over previous
#include <cuda_runtime.h>
#include <cuda_bf16.h>
#include <math.h>
#include <stdint.h>

constexpr int  NB   = 64;
constexpr long ROWS = 12544;

// ---------------- fp32 scratch ----------------
constexpr long O_Y=0, O_SC=O_Y+3211264, O_REA=O_SC+2458624, O_RE2=O_REA+3211264,
 O_PRE1=O_RE2+3211264, O_OUT=O_PRE1+3211264, O_R1=O_OUT+3211264, O_R2=O_R1+1605632,
 O_R3=O_R2+802816, O_R3T=O_R3+401408, O_PART=O_R3T+401408, O_RFC=O_PART+2097152,
 O_H1=O_RFC+200704, O_REX=O_H1+3211264, O_OUT1=O_REX+3211264, O_OT=O_OUT1+3211264,
 O_OFC=O_OT+3211264, O_BS1=O_OFC+65536, O_BS2=O_BS1+16384, O_MEAN=O_BS2+16384,
 O_ISTD=O_MEAN+256, O_SCAL=O_ISTD+256, O_FEND=O_SCAL+64;
__device__ float g_f[O_FEND];
__device__ int   g_pos[64];

// ---------------- bf16 scratch (2-segment [hi|lo] layout) ----------------
constexpr long B_ABIG=0;                                   // 16384 x 4608
constexpr long B_YAB = B_ABIG + 75497472L;                 // 64 x 256 x 512
constexpr long B_ATT = B_YAB + 8388608L;                   // 64 x 256 x 448
constexpr long B_YT  = B_ATT + 7340032L;                   // 64 x 256 x 448
constexpr long B_PW  = B_YT  + 7340032L;                   // 256 x 1536
constexpr long B_WO  = B_PW  + 393216L;                    // 256 x 512
constexpr long B_SH  = B_WO  + 131072L;
constexpr long B_RC1 = B_SH  + 131072L;                    // 128 x 4608
constexpr long B_RC2 = B_RC1 + 589824L;                    // 128 x 2304
constexpr long B_RC3 = B_RC2 + 294912L;                    // 128 x 1152
constexpr long B_EW1 = B_RC3 + 147456L;                    // 2048 x 4608
constexpr long B_EW2 = B_EW1 + 9437184L;
constexpr long B_HEND= B_EW2 + 9437184L;
__device__ __align__(1024) __nv_bfloat16 g_h[B_HEND];

// ---------------- helpers ----------------
__device__ __forceinline__ uint32_t smem_u32(const void* p) {
    uint32_t a;
    asm("{ .reg .u64 t; cvta.to.shared.u64 t, %1; cvt.u32.u64 %0, t; }" : "=r"(a) : "l"(p));
    return a;
}
__device__ __forceinline__ float geluf(float v) {
    return 0.5f * v * (1.0f + erff(v * 0.70710678118654752440f));
}
#define CP_ASYNC16(dst, src) \
    asm volatile("cp.async.ca.shared.global [%0], [%1], 16;" :: "r"(dst), "l"(src))
#define CP_COMMIT() asm volatile("cp.async.commit_group;" ::: "memory")
#define CP_WAIT1()  asm volatile("cp.async.wait_group 1;" ::: "memory")
#define LDSM_X4(r, addr) \
    asm volatile("ldmatrix.sync.aligned.m8n8.x4.shared.b16 {%0,%1,%2,%3}, [%4];" \
        : "=r"((r)[0]), "=r"((r)[1]), "=r"((r)[2]), "=r"((r)[3]) : "r"(addr))
__device__ __forceinline__ void mma16816(float* c, const uint32_t* a, uint32_t b0, uint32_t b1) {
    asm volatile("mma.sync.aligned.m16n8k16.row.col.f32.bf16.bf16.f32 "
        "{%0,%1,%2,%3}, {%4,%5,%6,%7}, {%8,%9}, {%0,%1,%2,%3};"
        : "+f"(c[0]), "+f"(c[1]), "+f"(c[2]), "+f"(c[3])
        : "r"(a[0]), "r"(a[1]), "r"(a[2]), "r"(a[3]), "r"(b0), "r"(b1));
}

// ---------------- tensor-core GEMM, 3-phase bf16x3 ----------------
// A [Mpad][2*Kseg] bf16 = [hi(Kseg)|lo(Kseg)], B [Npad][2*Kseg] same.
// C = act(alpha * (Ahi.Bhi^T + Ahi.Blo^T + Alo.Bhi^T) + bias) * zscale
// CTA tile 128x128, K-chunk 32, 3-stage cp.async, 1 barrier/iter.
constexpr int SSTR = 40;                       // padded smem stride (bf16)
constexpr uint32_t BUFB = 128 * SSTR * 2;      // bytes per matrix per stage
constexpr int SMEM_T = 6 * (int)BUFB;          // 61440

__global__ __launch_bounds__(256) void k_tgemm(
    const __nv_bfloat16* __restrict__ A, const __nv_bfloat16* __restrict__ Bm,
    float* __restrict__ C, int M, int N, int Kseg,
    long sA, long sB, long sC,
    const int* __restrict__ bIdx, const float* __restrict__ bias, long sBias,
    const float* __restrict__ zscale, float alpha, int act)
{
    extern __shared__ __align__(16) char smem[];
    const int tid = threadIdx.x, w = tid >> 5, lane = tid & 31;
    const int z = blockIdx.z, m0 = blockIdx.y * 128, n0 = blockIdx.x * 128;
    const int Ka = 2 * Kseg;

    A += (long)z * sA;
    const int bi = bIdx ? bIdx[z] : z;
    Bm += (long)bi * sB;
    C += (long)z * sC;
    const float* biasP = bias ? bias + (long)bi * sBias : nullptr;
    const float zs = zscale ? zscale[z] : 1.0f;

    const uint32_t saB = smem_u32(smem);
    const uint32_t sbB = saB + 3 * BUFB;

    const int wm = w & 3, wn = w >> 2;
    const int matId = lane >> 3;
    const int aRow = wm * 32 + (matId & 1) * 8 + (lane & 7);
    const int aCol = (matId >> 1) * 8;
    const int bRow = wn * 64 + (matId >> 1) * 8 + (lane & 7);
    const int bCol = (matId & 1) * 8;

    float acc[2][8][4];
#pragma unroll
    for (int i = 0; i < 2; i++)
#pragma unroll
        for (int j = 0; j < 8; j++)
#pragma unroll
            for (int e = 0; e < 4; e++) acc[i][j][e] = 0.0f;

    const int nk = Kseg >> 5;
    const int ntot = nk * 3;
    const int ldRow  = tid >> 2, ldC8 = (tid & 3) << 3;
    const int ldRow1 = (tid + 256) >> 2;

    auto issue = [&](int ch, int buf) {
        int phase = (ch >= nk) + (ch >= 2 * nk);
        int within = ch - phase * nk;
        int aOff = (phase == 2) ? Kseg : 0;
        int bOff = (phase == 1) ? Kseg : 0;
        const __nv_bfloat16* Ab = A + (long)m0 * Ka + aOff + (within << 5);
        const __nv_bfloat16* Bb = Bm + (long)n0 * Ka + bOff + (within << 5);
        const uint32_t bo = (uint32_t)buf * BUFB;
        CP_ASYNC16(saB + bo + (uint32_t)((ldRow  * SSTR + ldC8) * 2), Ab + (long)ldRow  * Ka + ldC8);
        CP_ASYNC16(sbB + bo + (uint32_t)((ldRow  * SSTR + ldC8) * 2), Bb + (long)ldRow  * Ka + ldC8);
        CP_ASYNC16(saB + bo + (uint32_t)((ldRow1 * SSTR + ldC8) * 2), Ab + (long)ldRow1 * Ka + ldC8);
        CP_ASYNC16(sbB + bo + (uint32_t)((ldRow1 * SSTR + ldC8) * 2), Bb + (long)ldRow1 * Ka + ldC8);
        CP_COMMIT();
    };

    issue(0, 0);
    issue(1, 1);
    CP_WAIT1();           // chunk 0 complete
    __syncthreads();

    for (int ch = 0; ch < ntot; ch++) {
        const int buf = ch % 3;
        if (ch + 2 < ntot) issue(ch + 2, (ch + 2) % 3);

        const uint32_t sa0 = saB + (uint32_t)buf * BUFB;
        const uint32_t sb0 = sbB + (uint32_t)buf * BUFB;
#pragma unroll
        for (int k16 = 0; k16 < 2; k16++) {
            uint32_t af[2][4];
#pragma unroll
            for (int mi = 0; mi < 2; mi++)
                LDSM_X4(af[mi], sa0 + (uint32_t)((((aRow + mi * 16) * SSTR) + aCol + k16 * 16) * 2));
            uint32_t bf[4][4];
#pragma unroll
            for (int nj = 0; nj < 4; nj++)
                LDSM_X4(bf[nj], sb0 + (uint32_t)((((bRow + nj * 16) * SSTR) + bCol + k16 * 16) * 2));
#pragma unroll
            for (int mi = 0; mi < 2; mi++)
#pragma unroll
                for (int nj = 0; nj < 4; nj++) {
                    mma16816(acc[mi][nj * 2],     af[mi], bf[nj][0], bf[nj][1]);
                    mma16816(acc[mi][nj * 2 + 1], af[mi], bf[nj][2], bf[nj][3]);
                }
        }
        CP_WAIT1();       // chunk ch+1 complete (if any outstanding)
        __syncthreads();  // publish + guard buffer reuse
    }

    // epilogue
#pragma unroll
    for (int mi = 0; mi < 2; mi++) {
#pragma unroll
        for (int nj2 = 0; nj2 < 8; nj2++) {
            int row0 = m0 + wm * 32 + mi * 16 + (lane >> 2);
            int col0 = n0 + wn * 64 + nj2 * 8 + (lane & 3) * 2;
#pragma unroll
            for (int half = 0; half < 2; half++) {
                int gm = row0 + half * 8;
                if (gm < M && col0 + 2 <= N) {
                    float2 o;
                    float v0 = acc[mi][nj2][half * 2]     * alpha;
                    float v1 = acc[mi][nj2][half * 2 + 1] * alpha;
                    if (biasP) { v0 += biasP[col0]; v1 += biasP[col0 + 1]; }
                    if (act) { v0 = geluf(v0); v1 = geluf(v1); }
                    o.x = v0 * zs; o.y = v1 * zs;
                    *(float2*)(C + (long)gm * N + col0) = o;
                }
            }
        }
    }
}

// ---------------- bf16 hi/lo expansion kernels (2-segment) ----------------
__device__ __forceinline__ __nv_bfloat16 pick_hl(float x, bool lo) {
    __nv_bfloat16 hi = __float2bfloat16(x);
    return lo ? __float2bfloat16(x - __bfloat162float(hi)) : hi;
}

// generic matrix -> [hi(Kseg)|lo(Kseg)]
__global__ void k_expand8(const float* __restrict__ src, __nv_bfloat16* __restrict__ dst,
                          int Rvalid, int Rpad, int K, int Kseg, long sSrc, int ld, int trans)
{
    long zr = blockIdx.y;
    int r = (int)(zr % Rpad), z = (int)(zr / Rpad);
    int kp0 = (blockIdx.x * blockDim.x + threadIdx.x) << 3;
    if (kp0 >= 2 * Kseg) return;
    bool lo = kp0 >= Kseg;
    int k0 = kp0 - (lo ? Kseg : 0);
    const float* sp = src + (long)z * sSrc;
    __nv_bfloat16 o[8];
#pragma unroll
    for (int j = 0; j < 8; j++) {
        int k = k0 + j;
        float x = 0.0f;
        if (r < Rvalid && k < K)
            x = trans ? sp[(long)k * ld + r] : sp[(long)r * ld + k];
        o[j] = pick_hl(x, lo);
    }
    *(uint4*)(dst + zr * (2L * Kseg) + kp0) = *(uint4*)o;
}

// fused im2col(3x3, pad1, 14x14) -> [hi|lo]; Cin power of 2, Kseg = 9*Cin
__global__ void k_exp_im2col3(const float* __restrict__ src, __nv_bfloat16* __restrict__ dst,
                              int Cin, int logC, int Kseg, int perBatch)
{
    long row = blockIdx.y;
    int b, s; bool rv = true;
    if (perBatch) { b = (int)(row >> 8); int rp = (int)(row & 255); rv = rp < 196; s = rp; }
    else          { b = (int)(row / 196); s = (int)(row % 196); }
    int kp0 = (blockIdx.x * blockDim.x + threadIdx.x) << 3;
    if (kp0 >= 2 * Kseg) return;
    bool lo = kp0 >= Kseg;
    int k = kp0 - (lo ? Kseg : 0);
    float xv[8];
#pragma unroll
    for (int j = 0; j < 8; j++) xv[j] = 0.0f;
    if (rv) {
        int off = k >> logC, c = k & (Cin - 1);
        int yy = s / 14, xx = s - yy * 14;
        int sy = yy + off / 3 - 1, sx = xx + off % 3 - 1;
        if ((unsigned)sy < 14u && (unsigned)sx < 14u) {
            const float* p = src + (((long)(b * 196 + sy * 14 + sx)) << logC) + c;
            float4 f0 = *(const float4*)p, f1 = *(const float4*)(p + 4);
            xv[0]=f0.x; xv[1]=f0.y; xv[2]=f0.z; xv[3]=f0.w;
            xv[4]=f1.x; xv[5]=f1.y; xv[6]=f1.z; xv[7]=f1.w;
        }
    }
    __nv_bfloat16 o[8];
#pragma unroll
    for (int j = 0; j < 8; j++) o[j] = pick_hl(xv[j], lo);
    *(uint4*)(dst + row * (2L * Kseg) + kp0) = *(uint4*)o;
}

// patch im2col(16x16 s16) -> [hi(768)|lo(768)]
__global__ void k_exp_patch(const float* __restrict__ x, __nv_bfloat16* __restrict__ dst)
{
    int row = blockIdx.y;
    int b = row / 196, s = row % 196;
    int ph = s / 14, pw = s - ph * 14;
    int kp0 = (blockIdx.x * blockDim.x + threadIdx.x) << 3;
    if (kp0 >= 1536) return;
    bool lo = kp0 >= 768;
    int k = kp0 - (lo ? 768 : 0);
    int c = k >> 8, ii = (k >> 4) & 15, jj = k & 15;
    const float* p = x + (((long)(b * 3 + c) * 224) + ph * 16 + ii) * 224 + pw * 16 + jj;
    float4 f0 = *(const float4*)p, f1 = *(const float4*)(p + 4);
    float xv[8] = {f0.x, f0.y, f0.z, f0.w, f1.x, f1.y, f1.z, f1.w};
    __nv_bfloat16 o[8];
#pragma unroll
    for (int j = 0; j < 8; j++) o[j] = pick_hl(xv[j], lo);
    *(uint4*)(dst + (long)row * 1536 + kp0) = *(uint4*)o;
}

// 3x3 weights [Nout][Cin][9] -> [Npad][hi|lo], k = off*Cin + c
__global__ void k_exp_w3x3(const float* __restrict__ src, __nv_bfloat16* __restrict__ dst,
                           int Nout, int Cin, int logC, int Kseg)
{
    int n = blockIdx.y;
    int kp0 = (blockIdx.x * blockDim.x + threadIdx.x) << 3;
    if (kp0 >= 2 * Kseg) return;
    bool lo = kp0 >= Kseg;
    int k = kp0 - (lo ? Kseg : 0);
    int off = k >> logC, c = k & (Cin - 1);
    bool inb = (n < Nout);
    __nv_bfloat16 o[8];
#pragma unroll
    for (int j = 0; j < 8; j++) {
        float xx = inb ? src[((long)n * Cin + c + j) * 9 + off] : 0.0f;
        o[j] = pick_hl(xx, lo);
    }
    *(uint4*)(dst + (long)n * (2L * Kseg) + kp0) = *(uint4*)o;
}

// ---------------- FFMA split-K (skinny M=64) ----------------
__device__ __forceinline__ unsigned long long pk2(float a, float b) {
    unsigned long long r;
    asm("mov.b64 %0, {%1, %2};" : "=l"(r) : "f"(a), "f"(b));
    return r;
}
__device__ __forceinline__ void fma2(unsigned long long& d,
                                     unsigned long long a, unsigned long long b) {
    asm("fma.rn.f32x2 %0, %1, %2, %0;" : "+l"(d) : "l"(a), "l"(b));
}
__device__ __forceinline__ float2 up2(unsigned long long v) {
    float a, b;
    asm("mov.b64 {%0, %1}, %2;" : "=f"(a), "=f"(b) : "l"(v));
    return make_float2(a, b);
}

__global__ __launch_bounds__(256) void k_gemm_split(
    const float* __restrict__ A, const float* __restrict__ Bm, float* __restrict__ C,
    int M, int N, int K, int nsplit)
{
    __shared__ __align__(16) float As[16][68];
    __shared__ __align__(16) float Bs[16][68];
    const int z = blockIdx.z;
    int kc = (K + nsplit - 1) / nsplit;
    int kBeg = z * kc, kEnd = min(K, kBeg + kc);
    C += (long)z * M * N;
    const int tid = threadIdx.x;
    const int m0 = blockIdx.y * 64, n0 = blockIdx.x * 64;
    const int tr = tid >> 4, tc = tid & 15;
    unsigned long long acc[4][2];
#pragma unroll
    for (int i = 0; i < 4; i++) { acc[i][0] = 0ULL; acc[i][1] = 0ULL; }
    for (int k0 = kBeg; k0 < kEnd; k0 += 16) {
#pragma unroll
        for (int i = 0; i < 4; i++) {
            int f = tid + i * 256;
            int m = f >> 4, kk = f & 15;
            int gm = m0 + m, gk = k0 + kk;
            As[kk][m] = (gm < M && gk < kEnd) ? A[(long)gm * K + gk] : 0.0f;
            int gn = n0 + m;
            Bs[kk][m] = (gn < N && gk < kEnd) ? Bm[(long)gn * K + gk] : 0.0f;
        }
        __syncthreads();
#pragma unroll
        for (int kk = 0; kk < 16; kk++) {
            float4 av = *(const float4*)&As[kk][tr * 4];
            ulonglong2 bp = *(const ulonglong2*)&Bs[kk][tc * 4];
            unsigned long long a0 = pk2(av.x, av.x), a1 = pk2(av.y, av.y);
            unsigned long long a2 = pk2(av.z, av.z), a3 = pk2(av.w, av.w);
            fma2(acc[0][0], a0, bp.x); fma2(acc[0][1], a0, bp.y);
            fma2(acc[1][0], a1, bp.x); fma2(acc[1][1], a1, bp.y);
            fma2(acc[2][0], a2, bp.x); fma2(acc[2][1], a2, bp.y);
            fma2(acc[3][0], a3, bp.x); fma2(acc[3][1], a3, bp.y);
        }
        __syncthreads();
    }
#pragma unroll
    for (int i = 0; i < 4; i++) {
        int gm = m0 + tr * 4 + i;
        if (gm >= M) continue;
#pragma unroll
        for (int jp = 0; jp < 2; jp++) {
            float2 v = up2(acc[i][jp]);
            int gn = n0 + tc * 4 + jp * 2;
            if (gn < N)     C[(long)gm * N + gn] = v.x;
            if (gn + 1 < N) C[(long)gm * N + gn + 1] = v.y;
        }
    }
}

// ---------------- small kernels ----------------
__global__ void k_addpos(float* __restrict__ y, const float* __restrict__ pos) {
    long total = ROWS * 256;
    for (long i = blockIdx.x * (long)blockDim.x + threadIdx.x; i < total;
         i += (long)gridDim.x * blockDim.x)
        y[i] += pos[i % (196 * 256)];
}
__global__ void k_add(float* __restrict__ dst, const float* __restrict__ a,
                      const float* __restrict__ b, long n) {
    for (long i = blockIdx.x * (long)blockDim.x + threadIdx.x; i < n;
         i += (long)gridDim.x * blockDim.x)
        dst[i] = a[i] + b[i];
}
__global__ void k_softmax(float* __restrict__ sc) {
    long row = blockIdx.x;
    float* p = sc + row * 196;
    int t = threadIdx.x;
    __shared__ float red[256];
    float v = (t < 196) ? p[t] : -3.4e38f;
    red[t] = v; __syncthreads();
    for (int s = 128; s > 0; s >>= 1) { if (t < s) red[t] = fmaxf(red[t], red[t + s]); __syncthreads(); }
    float mx = red[0]; __syncthreads();
    float ex = (t < 196) ? expf(v - mx) : 0.0f;
    red[t] = ex; __syncthreads();
    for (int s = 128; s > 0; s >>= 1) { if (t < s) red[t] += red[t + s]; __syncthreads(); }
    float inv = 1.0f / red[0];
    if (t < 196) p[t] = ex * inv;
}
__global__ void k_bnstat(const float* __restrict__ x, float* __restrict__ psum,
                         float* __restrict__ psq) {
    int c = threadIdx.x, ch = blockIdx.x;
    float s = 0.0f, q = 0.0f;
    long r0 = (long)ch * 196;
    for (int r = 0; r < 196; r++) {
        float v = x[(r0 + r) * 256 + c];
        s += v; q += v * v;
    }
    psum[ch * 256 + c] = s; psq[ch * 256 + c] = q;
}
__global__ void k_bnfin(const float* __restrict__ psum, const float* __restrict__ psq,
                        float* __restrict__ mean, float* __restrict__ istd) {
    int c = threadIdx.x;
    float s = 0.0f, q = 0.0f;
    for (int i = 0; i < 64; i++) { s += psum[i * 256 + c]; q += psq[i * 256 + c]; }
    float m = s / 12544.0f;
    float var = q / 12544.0f - m * m;
    mean[c] = m; istd[c] = rsqrtf(var + 1e-5f);
}
__global__ void k_bnnorm(const float* __restrict__ x, float* __restrict__ out,
                         const float* __restrict__ mean, const float* __restrict__ istd,
                         const float* __restrict__ g, const float* __restrict__ b,
                         int transposed) {
    long total = ROWS * 256;
    for (long i = blockIdx.x * (long)blockDim.x + threadIdx.x; i < total;
         i += (long)gridDim.x * blockDim.x) {
        int c = (int)(i & 255);
        long row = i >> 8;
        float v = (x[i] - mean[c]) * istd[c] * g[c] + b[c];
        if (!transposed) out[i] = v;
        else {
            int bb = (int)(row / 196), ss = (int)(row % 196);
            out[(long)bb * 50176 + c * 196 + ss] = v;
        }
    }
}
__global__ void k_tr32(const float* __restrict__ src, float* __restrict__ dst) {
    long total = ROWS * 32;
    for (long i = blockIdx.x * (long)blockDim.x + threadIdx.x; i < total;
         i += (long)gridDim.x * blockDim.x) {
        int b = (int)(i / 6272), r = (int)(i % 6272);
        int c = r / 196, s = r % 196;
        dst[i] = src[((long)(b * 196 + s)) * 32 + c];
    }
}
__global__ void k_reduce(const float* __restrict__ part, float* __restrict__ out,
                         int M, int N, int nsplit, const float* __restrict__ bias, int act) {
    long total = (long)M * N;
    for (long i = blockIdx.x * (long)blockDim.x + threadIdx.x; i < total;
         i += (long)gridDim.x * blockDim.x) {
        int n = (int)(i % N);
        float s = 0.0f;
        for (int p = 0; p < nsplit; p++) s += part[(long)p * total + i];
        if (bias) s += bias[n];
        if (act) s = geluf(s);
        out[i] = s;
    }
}
__global__ void k_rd2(const float* __restrict__ rfc, const float* __restrict__ w,
                      const float* __restrict__ b, int* __restrict__ pos,
                      float* __restrict__ scale) {
    int bb = blockIdx.x, t = threadIdx.x;
    int e = t >> 5, lane = t & 31;
    const float* xr = rfc + (long)bb * 3136;
    const float* wr = w + (long)e * 3136;
    float s = 0.0f;
    for (int k = lane; k < 3136; k += 32) s += xr[k] * wr[k];
    for (int o = 16; o > 0; o >>= 1) s += __shfl_down_sync(0xffffffffu, s, o);
    __shared__ float lg[8];
    if (lane == 0) lg[e] = s + b[e];
    __syncthreads();
    if (t == 0) {
        int best = 0; float bv = lg[0];
        for (int e2 = 1; e2 < 8; e2++) if (lg[e2] > bv) { bv = lg[e2]; best = e2; }
        pos[bb] = best; scale[bb] = bv;
    }
}

// ---------------- host ----------------
static inline int GS(long n) { return (int)((n + 255) / 256); }

static void tgemm(const __nv_bfloat16* A, const __nv_bfloat16* B, float* C,
                  int M, int Mpad, int N, int Npad, int Kseg, int Z,
                  long sA, long sB, long sC,
                  const int* bIdx, const float* bias, long sBias,
                  const float* zscale, float alpha, int act) {
    cudaFuncSetAttribute(k_tgemm, cudaFuncAttributeMaxDynamicSharedMemorySize, SMEM_T);
    dim3 g(Npad / 128, Mpad / 128, Z);
    k_tgemm<<<g, 256, SMEM_T>>>(A, B, C, M, N, Kseg, sA, sB, sC,
                                bIdx, bias, sBias, zscale, alpha, act);
}
static void expand8(const float* src, __nv_bfloat16* dst, int Rvalid, int Rpad,
                    int K, int Kseg, long sSrc, int ld, int trans, int Z) {
    dim3 g((2 * Kseg / 8 + 127) / 128, Z * Rpad);
    k_expand8<<<g, 128>>>(src, dst, Rvalid, Rpad, K, Kseg, sSrc, ld, trans);
}
static void exp_im2col3(const float* src, __nv_bfloat16* dst, int Cin, int logC,
                        int Kseg, int perBatch) {
    dim3 g((2 * Kseg / 8 + 127) / 128, perBatch ? 16384 : 12544);
    k_exp_im2col3<<<g, 128>>>(src, dst, Cin, logC, Kseg, perBatch);
}

extern "C" void kernel_launch(void* const* d_in, const int* in_sizes, int n_in,
                              void* d_out, int out_size) {
    const float* x       = (const float*)d_in[0];
    const float* patch_w = (const float*)d_in[1];
    const float* patch_b = (const float*)d_in[2];
    const float* pos_emb = (const float*)d_in[3];
    const float* wo_w    = (const float*)d_in[4];
    const float* wo_b    = (const float*)d_in[5];
    const float* bn1_g   = (const float*)d_in[6];
    const float* bn1_b   = (const float*)d_in[7];
    const float* rc1_w   = (const float*)d_in[8];
    const float* rc1_b   = (const float*)d_in[9];
    const float* rc2_w   = (const float*)d_in[10];
    const float* rc2_b   = (const float*)d_in[11];
    const float* rc3_w   = (const float*)d_in[12];
    const float* rc3_b   = (const float*)d_in[13];
    const float* rd1_w   = (const float*)d_in[14];
    const float* rd1_b   = (const float*)d_in[15];
    const float* rd2_w   = (const float*)d_in[16];
    const float* rd2_b   = (const float*)d_in[17];
    const float* exp_w1  = (const float*)d_in[18];
    const float* exp_b1  = (const float*)d_in[19];
    const float* exp_w2  = (const float*)d_in[20];
    const float* exp_b2  = (const float*)d_in[21];
    const float* shard_w = (const float*)d_in[22];
    const float* shard_b = (const float*)d_in[23];
    const float* bn2_g   = (const float*)d_in[24];
    const float* bn2_b   = (const float*)d_in[25];
    const float* od1_w   = (const float*)d_in[26];
    const float* od1_b   = (const float*)d_in[27];
    const float* od2_w   = (const float*)d_in[28];
    const float* od2_b   = (const float*)d_in[29];

    float* F = nullptr;            cudaGetSymbolAddress((void**)&F, g_f);
    __nv_bfloat16* Hh = nullptr;   cudaGetSymbolAddress((void**)&Hh, g_h);
    int* posP = nullptr;           cudaGetSymbolAddress((void**)&posP, g_pos);

    float *Y = F + O_Y, *sc = F + O_SC, *reA = F + O_REA, *re2 = F + O_RE2;
    float *pre1 = F + O_PRE1, *outb = F + O_OUT, *r1 = F + O_R1, *r2 = F + O_R2;
    float *r3 = F + O_R3, *r3t = F + O_R3T, *part = F + O_PART, *rfc = F + O_RFC;
    float *h1 = F + O_H1, *rexp = F + O_REX, *out1 = F + O_OUT1, *ot = F + O_OT;
    float *ofc = F + O_OFC, *bs1 = F + O_BS1, *bs2 = F + O_BS2;
    float *meanp = F + O_MEAN, *istdp = F + O_ISTD, *scalp = F + O_SCAL;

    __nv_bfloat16 *ABig = Hh + B_ABIG, *YAB = Hh + B_YAB, *ATT = Hh + B_ATT;
    __nv_bfloat16 *YT = Hh + B_YT, *PW = Hh + B_PW, *WO = Hh + B_WO, *SH = Hh + B_SH;
    __nv_bfloat16 *RC1 = Hh + B_RC1, *RC2 = Hh + B_RC2, *RC3 = Hh + B_RC3;
    __nv_bfloat16 *EW1 = Hh + B_EW1, *EW2 = Hh + B_EW2;

    const float inv14 = 1.0f / sqrtf(14.0f);

    // weight expansions ([hi|lo])
    expand8(patch_w, PW, 256, 256, 768, 768, 0, 768, 0, 1);
    expand8(wo_w,    WO, 256, 256, 256, 256, 0, 256, 0, 1);
    expand8(shard_w, SH, 256, 256, 256, 256, 0, 256, 0, 1);
    { dim3 g(5, 128);  k_exp_w3x3<<<g, 128>>>(rc1_w, RC1, 128, 256, 8, 2304); }
    { dim3 g(3, 128);  k_exp_w3x3<<<g, 128>>>(rc2_w, RC2, 64, 128, 7, 1152); }
    { dim3 g(2, 128);  k_exp_w3x3<<<g, 128>>>(rc3_w, RC3, 32, 64, 6, 576); }
    { dim3 g(5, 2048); k_exp_w3x3<<<g, 128>>>(exp_w1, EW1, 2048, 256, 8, 2304); }
    { dim3 g(5, 2048); k_exp_w3x3<<<g, 128>>>(exp_w2, EW2, 2048, 256, 8, 2304); }

    // patch embed -> Y
    { dim3 g(2, 12544); k_exp_patch<<<g, 128>>>(x, ABig); }
    tgemm(ABig, PW, Y, 12544, 12544, 256, 256, 768, 1, 0, 0, 0,
          nullptr, patch_b, 0, nullptr, 1.0f, 0);
    k_addpos<<<GS(ROWS * 256), 256>>>(Y, pos_emb);

    // attention (Q and K share the same expanded buffer)
    expand8(Y, YAB, 196, 256, 256, 256, 196 * 256, 256, 0, 64);
    tgemm(YAB, YAB, sc, 196, 256, 196, 256, 256, 64, 256L * 512, 256L * 512, 196L * 196,
          nullptr, nullptr, 0, nullptr, inv14, 0);
    k_softmax<<<12544, 256>>>(sc);
    expand8(sc, ATT, 196, 256, 196, 224, 196 * 196, 196, 0, 64);
    expand8(Y, YT, 256, 256, 196, 224, 196 * 256, 256, 1, 64);
    tgemm(ATT, YT, reA, 196, 256, 256, 256, 224, 64, 256L * 448, 256L * 448, 196L * 256,
          nullptr, nullptr, 0, nullptr, 1.0f, 0);
    expand8(reA, ABig, 12544, 12544, 256, 256, 0, 256, 0, 1);
    tgemm(ABig, WO, re2, 12544, 12544, 256, 256, 256, 1, 0, 0, 0,
          nullptr, wo_b, 0, nullptr, 1.0f, 0);
    k_add<<<GS(ROWS * 256), 256>>>(pre1, Y, re2, ROWS * 256);

    // bn1
    k_bnstat<<<64, 256>>>(pre1, bs1, bs2);
    k_bnfin<<<1, 256>>>(bs1, bs2, meanp, istdp);
    k_bnnorm<<<GS(ROWS * 256), 256>>>(pre1, outb, meanp, istdp, bn1_g, bn1_b, 0);

    // router convs
    exp_im2col3(outb, ABig, 256, 8, 2304, 0);
    tgemm(ABig, RC1, r1, 12544, 12544, 128, 128, 2304, 1, 0, 0, 0,
          nullptr, rc1_b, 0, nullptr, 1.0f, 1);
    exp_im2col3(r1, ABig, 128, 7, 1152, 0);
    tgemm(ABig, RC2, r2, 12544, 12544, 64, 128, 1152, 1, 0, 0, 0,
          nullptr, rc2_b, 0, nullptr, 1.0f, 1);
    exp_im2col3(r2, ABig, 64, 6, 576, 0);
    tgemm(ABig, RC3, r3, 12544, 12544, 32, 128, 576, 1, 0, 0, 0,
          nullptr, rc3_b, 0, nullptr, 1.0f, 1);
    k_tr32<<<GS(ROWS * 32), 256>>>(r3, r3t);

    // router dense (FFMA split-K) + argmax gate
    { dim3 g(49, 1, 8); k_gemm_split<<<g, 256>>>(r3t, rd1_w, part, 64, 3136, 6272, 8); }
    k_reduce<<<GS(64L * 3136), 256>>>(part, rfc, 64, 3136, 8, rd1_b, 1);
    k_rd2<<<64, 256>>>(rfc, rd2_w, rd2_b, posP, scalp);

    // shard shortcut (uses ABig before experts overwrite it)
    expand8(outb, ABig, 12544, 12544, 256, 256, 0, 256, 0, 1);
    tgemm(ABig, SH, out1, 12544, 12544, 256, 256, 256, 1, 0, 0, 0,
          nullptr, shard_b, 0, nullptr, 1.0f, 0);

    // experts
    exp_im2col3(re2, ABig, 256, 8, 2304, 1);
    tgemm(ABig, EW1, h1, 196, 256, 256, 256, 2304, 64,
          256L * 4608, 256L * 4608, 196L * 256, posP, exp_b1, 256, nullptr, 1.0f, 1);
    exp_im2col3(h1, ABig, 256, 8, 2304, 1);
    tgemm(ABig, EW2, rexp, 196, 256, 256, 256, 2304, 64,
          256L * 4608, 256L * 4608, 196L * 256, posP, exp_b2, 256, scalp, 1.0f, 1);

    // sum + bn2 (transposed write [b][c][s])
    k_add<<<GS(ROWS * 256), 256>>>(rexp, rexp, out1, ROWS * 256);
    k_bnstat<<<64, 256>>>(rexp, bs1, bs2);
    k_bnfin<<<1, 256>>>(bs1, bs2, meanp, istdp);
    k_bnnorm<<<GS(ROWS * 256), 256>>>(rexp, ot, meanp, istdp, bn2_g, bn2_b, 1);

    // output head (FFMA split-K)
    { dim3 g(16, 1, 32); k_gemm_split<<<g, 256>>>(ot, od1_w, part, 64, 1024, 50176, 32); }
    k_reduce<<<GS(64L * 1024), 256>>>(part, ofc, 64, 1024, 32, od1_b, 1);
    { dim3 g(16, 1, 8); k_gemm_split<<<g, 256>>>(ofc, od2_w, part, 64, 1000, 1024, 8); }
    k_reduce<<<GS(64L * 1000), 256>>>(part, (float*)d_out, 64, 1000, 8, od2_b, 0);
}